// round 1
// baseline (speedup 1.0000x reference)
#include <cuda_runtime.h>
#include <math.h>

#define NN 50000
#define NE 1600000
#define HH 4
#define FF 128

// ---------------- scratch (device globals: allowed; no runtime alloc) -------
__device__ int   g_is64;
__device__ int   g_src[NE];
__device__ int   g_dst[NE];
__device__ int   g_deg[NN];
__device__ int   g_off[NN + 1];
__device__ int   g_cursor[NN];
__device__ float4 g_ssrc[NN];
__device__ float4 g_sdst[NN];
__device__ int    g_sorted_dst[NE];
__device__ float4 g_sorted_w[NE];

// ---------------- 1) detect int64 vs int32 edge_index -----------------------
// int64 nonneg indices < 50000 => every odd 32-bit word is 0.
// int32 random indices => odd words are random in [0,50000): P(all 4096 zero)~0.
__global__ void k_detect(const int* __restrict__ ei_words) {
    __shared__ int bad;
    if (threadIdx.x == 0) bad = 0;
    __syncthreads();
    for (int i = threadIdx.x; i < 4096; i += blockDim.x) {
        if (ei_words[2 * i + 1] != 0) bad = 1;
    }
    __syncthreads();
    if (threadIdx.x == 0) g_is64 = (bad == 0) ? 1 : 0;
}

// ---------------- 2) convert to int32 src/dst, zero degree ------------------
__global__ void k_convert(const void* __restrict__ ei) {
    int i = blockIdx.x * blockDim.x + threadIdx.x;
    if (i >= NE) return;
    if (g_is64) {
        const long long* p = (const long long*)ei;
        g_src[i] = (int)p[i];
        g_dst[i] = (int)p[NE + i];
    } else {
        const int* p = (const int*)ei;
        g_src[i] = p[i];
        g_dst[i] = p[NE + i];
    }
    if (i < NN) g_deg[i] = 0;
}

// ---------------- 3) degree histogram ---------------------------------------
__global__ void k_hist() {
    int i = blockIdx.x * blockDim.x + threadIdx.x;
    if (i >= NE) return;
    atomicAdd(&g_deg[g_src[i]], 1);
}

// ---------------- 4) exclusive scan (single block, 1024 threads) ------------
__global__ void k_scan() {
    __shared__ int wsum[32];
    int tid = threadIdx.x, lane = tid & 31, wid = tid >> 5;
    int carry = 0;
    for (int base = 0; base < NN; base += 1024) {
        int i = base + tid;
        int v = (i < NN) ? g_deg[i] : 0;
        int inc = v;
        #pragma unroll
        for (int o = 1; o < 32; o <<= 1) {
            int t = __shfl_up_sync(0xffffffffu, inc, o);
            if (lane >= o) inc += t;
        }
        if (lane == 31) wsum[wid] = inc;
        __syncthreads();
        if (wid == 0) {
            int t = wsum[lane];
            #pragma unroll
            for (int o = 1; o < 32; o <<= 1) {
                int u = __shfl_up_sync(0xffffffffu, t, o);
                if (lane >= o) t += u;
            }
            wsum[lane] = t;
        }
        __syncthreads();
        int woff = wid ? wsum[wid - 1] : 0;
        int excl = carry + woff + inc - v;
        if (i < NN) { g_off[i] = excl; g_cursor[i] = excl; }
        carry += wsum[31];
        __syncthreads();
    }
    if (tid == 0) g_off[NN] = carry;
}

// ---------------- 5) per-node attention scores s_src/s_dst ------------------
// s_src[h,n] = sum_f x[n,f]*w[h,f]*a[h,f],  s_dst uses a[h,128+f]
__global__ void k_scores(const float* __restrict__ x,
                         const float* __restrict__ wp,
                         const float* __restrict__ ap) {
    int gw   = (blockIdx.x * blockDim.x + threadIdx.x) >> 5;
    int lane = threadIdx.x & 31;
    if (gw >= NN) return;
    int f = lane * 4;
    float4 xv = *(const float4*)(x + (size_t)gw * FF + f);
    float ss[HH], sd[HH];
    #pragma unroll
    for (int h = 0; h < HH; h++) {
        float4 wv = *(const float4*)(wp + h * FF + f);
        float4 as = *(const float4*)(ap + h * 2 * FF + f);
        float4 ad = *(const float4*)(ap + h * 2 * FF + FF + f);
        float4 hw = make_float4(xv.x * wv.x, xv.y * wv.y, xv.z * wv.z, xv.w * wv.w);
        float hs = hw.x * as.x + hw.y * as.y + hw.z * as.z + hw.w * as.w;
        float hd = hw.x * ad.x + hw.y * ad.y + hw.z * ad.z + hw.w * ad.w;
        #pragma unroll
        for (int o = 16; o; o >>= 1) {
            hs += __shfl_xor_sync(0xffffffffu, hs, o);
            hd += __shfl_xor_sync(0xffffffffu, hd, o);
        }
        ss[h] = hs; sd[h] = hd;
    }
    if (lane == 0) {
        g_ssrc[gw] = make_float4(ss[0], ss[1], ss[2], ss[3]);
        g_sdst[gw] = make_float4(sd[0], sd[1], sd[2], sd[3]);
    }
}

// ---------------- 6) scatter edges into CSR, precompute weights -------------
__device__ __forceinline__ float edge_w(float s) {
    // exp(-leaky_relu(s, 0.2)) ; -lrelu(s) = min(-s, -0.2s)
    return __expf(fminf(-s, -0.2f * s));
}
__global__ void k_scatter() {
    int i = blockIdx.x * blockDim.x + threadIdx.x;
    if (i >= NE) return;
    int s = g_src[i], d = g_dst[i];
    float4 a4 = g_ssrc[s];
    float4 b4 = g_sdst[d];
    float4 w4 = make_float4(edge_w(a4.x + b4.x), edge_w(a4.y + b4.y),
                            edge_w(a4.z + b4.z), edge_w(a4.w + b4.w));
    int pos = atomicAdd(&g_cursor[s], 1);
    g_sorted_dst[pos] = d;
    g_sorted_w[pos]   = w4;
}

// ---------------- 7) per-node aggregation (one warp / node) -----------------
__global__ void __launch_bounds__(256) k_agg(const float* __restrict__ x,
                                             const float* __restrict__ wp,
                                             float* __restrict__ out) {
    int gw   = (blockIdx.x * blockDim.x + threadIdx.x) >> 5;
    int lane = threadIdx.x & 31;
    if (gw >= NN) return;
    int beg = g_off[gw], end = g_off[gw + 1];
    int f = lane * 4;

    float4 a0 = make_float4(0.f, 0.f, 0.f, 0.f), a1 = a0, a2 = a0, a3 = a0;
    float4 rs = a0;

    int d = 0;
    float4 e4 = make_float4(0.f, 0.f, 0.f, 0.f);
    if (beg < end) { d = g_sorted_dst[beg]; e4 = g_sorted_w[beg]; }

    for (int j = beg; j < end; ++j) {
        int dn = d;
        float4 en = e4;
        if (j + 1 < end) { dn = g_sorted_dst[j + 1]; en = g_sorted_w[j + 1]; }
        float4 xv = *(const float4*)(x + (size_t)d * FF + f);
        rs.x += e4.x; rs.y += e4.y; rs.z += e4.z; rs.w += e4.w;
        a0.x += e4.x * xv.x; a0.y += e4.x * xv.y; a0.z += e4.x * xv.z; a0.w += e4.x * xv.w;
        a1.x += e4.y * xv.x; a1.y += e4.y * xv.y; a1.z += e4.y * xv.z; a1.w += e4.y * xv.w;
        a2.x += e4.z * xv.x; a2.y += e4.z * xv.y; a2.z += e4.z * xv.z; a2.w += e4.z * xv.w;
        a3.x += e4.w * xv.x; a3.y += e4.w * xv.y; a3.z += e4.w * xv.z; a3.w += e4.w * xv.w;
        d = dn; e4 = en;
    }

    float i0 = 1.0f / rs.x, i1 = 1.0f / rs.y, i2 = 1.0f / rs.z, i3 = 1.0f / rs.w;
    float4 w0 = *(const float4*)(wp + 0 * FF + f);
    float4 w1 = *(const float4*)(wp + 1 * FF + f);
    float4 w2 = *(const float4*)(wp + 2 * FF + f);
    float4 w3 = *(const float4*)(wp + 3 * FF + f);

    size_t base = (size_t)gw * FF + f;
    *(float4*)(out + 0 * (size_t)NN * FF + base) =
        make_float4(a0.x * w0.x * i0, a0.y * w0.y * i0, a0.z * w0.z * i0, a0.w * w0.w * i0);
    *(float4*)(out + 1 * (size_t)NN * FF + base) =
        make_float4(a1.x * w1.x * i1, a1.y * w1.y * i1, a1.z * w1.z * i1, a1.w * w1.w * i1);
    *(float4*)(out + 2 * (size_t)NN * FF + base) =
        make_float4(a2.x * w2.x * i2, a2.y * w2.y * i2, a2.z * w2.z * i2, a2.w * w2.w * i2);
    *(float4*)(out + 3 * (size_t)NN * FF + base) =
        make_float4(a3.x * w3.x * i3, a3.y * w3.y * i3, a3.z * w3.z * i3, a3.w * w3.w * i3);
}

// ---------------- launch -----------------------------------------------------
extern "C" void kernel_launch(void* const* d_in, const int* in_sizes, int n_in,
                              void* d_out, int out_size) {
    const float* x  = (const float*)d_in[0];
    const float* wp = (const float*)d_in[1];
    const float* ap = (const float*)d_in[2];
    const void*  ei = d_in[3];
    float* out = (float*)d_out;

    const int TB = 256;
    int edge_blocks = (NE + TB - 1) / TB;           // 6250
    int node_blocks = (NN * 32 + TB - 1) / TB;      // 6250

    k_detect<<<1, 256>>>((const int*)ei);
    k_convert<<<edge_blocks, TB>>>(ei);
    k_hist<<<edge_blocks, TB>>>();
    k_scan<<<1, 1024>>>();
    k_scores<<<node_blocks, TB>>>(x, wp, ap);
    k_scatter<<<edge_blocks, TB>>>();
    k_agg<<<node_blocks, TB>>>(x, wp, out);
}

// round 2
// speedup vs baseline: 1.2954x; 1.2954x over previous
#include <cuda_runtime.h>
#include <math.h>

#define NN 50000
#define NE 1600000
#define HH 4
#define FF 128
#define NBLK 49   // ceil(50000/1024)

// ---------------- scratch ----------------------------------------------------
__device__ int    g_is64;
__device__ int    g_deg[NN];
__device__ int    g_off[NN + 1];
__device__ int    g_cursor[NN];
__device__ int    g_bsum[64];
__device__ int    g_boff[64];
__device__ float4 g_ssrc[NN];
__device__ float4 g_sdst[NN];
__device__ int    g_sorted_dst[NE];
__device__ float4 g_sorted_w[NE];

// unified edge-index fetch (handles int64 or int32 on-device layout)
__device__ __forceinline__ int EDGE_SRC(const int* p, int i, int is64) {
    return is64 ? p[2 * i] : p[i];
}
__device__ __forceinline__ int EDGE_DST(const int* p, int i, int is64) {
    return is64 ? p[2 * (NE + i)] : p[NE + i];
}

// ---------------- 1) init: zero degrees + dtype detect (block 0) -------------
__global__ void k_init(const int* __restrict__ ei_words) {
    int i = blockIdx.x * blockDim.x + threadIdx.x;
    if (i < NN) g_deg[i] = 0;
    if (blockIdx.x == 0) {
        __shared__ int bad;
        if (threadIdx.x == 0) bad = 0;
        __syncthreads();
        for (int k = threadIdx.x; k < 4096; k += blockDim.x)
            if (ei_words[2 * k + 1] != 0) bad = 1;
        __syncthreads();
        if (threadIdx.x == 0) g_is64 = (bad == 0) ? 1 : 0;
    }
}

// ---------------- 2) degree histogram (reads ei directly) --------------------
__global__ void k_hist(const int* __restrict__ ei) {
    int i = blockIdx.x * blockDim.x + threadIdx.x;
    if (i >= NE) return;
    atomicAdd(&g_deg[EDGE_SRC(ei, i, g_is64)], 1);
}

// ---------------- 3a) per-block degree sums ----------------------------------
__global__ void k_bsum() {
    __shared__ int wsum[32];
    int b = blockIdx.x, t = threadIdx.x, lane = t & 31, wid = t >> 5;
    int i = b * 1024 + t;
    int v = (i < NN) ? g_deg[i] : 0;
    #pragma unroll
    for (int o = 16; o; o >>= 1) v += __shfl_xor_sync(0xffffffffu, v, o);
    if (lane == 0) wsum[wid] = v;
    __syncthreads();
    if (wid == 0) {
        int s = wsum[lane];
        #pragma unroll
        for (int o = 16; o; o >>= 1) s += __shfl_xor_sync(0xffffffffu, s, o);
        if (lane == 0) g_bsum[b] = s;
    }
}

// ---------------- 3b) scan the 49 block sums (1 block, 64 thr) ---------------
__global__ void k_bscan() {
    __shared__ int w0tot;
    int t = threadIdx.x, lane = t & 31;
    int v = (t < NBLK) ? g_bsum[t] : 0;
    int inc = v;
    #pragma unroll
    for (int o = 1; o < 32; o <<= 1) {
        int u = __shfl_up_sync(0xffffffffu, inc, o);
        if (lane >= o) inc += u;
    }
    if (t == 31) w0tot = inc;
    __syncthreads();
    if (t >= 32) inc += w0tot;
    if (t < NBLK) g_boff[t] = inc - v;
    if (t == NBLK - 1) g_off[NN] = inc;
}

// ---------------- 3c) per-block exclusive scan + add block offset ------------
__global__ void k_scan3() {
    __shared__ int wsum[32];
    int b = blockIdx.x, t = threadIdx.x, lane = t & 31, wid = t >> 5;
    int i = b * 1024 + t;
    int v = (i < NN) ? g_deg[i] : 0;
    int inc = v;
    #pragma unroll
    for (int o = 1; o < 32; o <<= 1) {
        int u = __shfl_up_sync(0xffffffffu, inc, o);
        if (lane >= o) inc += u;
    }
    if (lane == 31) wsum[wid] = inc;
    __syncthreads();
    if (wid == 0) {
        int s = wsum[lane];
        #pragma unroll
        for (int o = 1; o < 32; o <<= 1) {
            int u = __shfl_up_sync(0xffffffffu, s, o);
            if (lane >= o) s += u;
        }
        wsum[lane] = s;
    }
    __syncthreads();
    int excl = g_boff[b] + (wid ? wsum[wid - 1] : 0) + inc - v;
    if (i < NN) { g_off[i] = excl; g_cursor[i] = excl; }
}

// ---------------- 4) per-node attention scores -------------------------------
__global__ void k_scores(const float* __restrict__ x,
                         const float* __restrict__ wp,
                         const float* __restrict__ ap) {
    int gw   = (blockIdx.x * blockDim.x + threadIdx.x) >> 5;
    int lane = threadIdx.x & 31;
    if (gw >= NN) return;
    int f = lane * 4;
    float4 xv = *(const float4*)(x + (size_t)gw * FF + f);
    float ss[HH], sd[HH];
    #pragma unroll
    for (int h = 0; h < HH; h++) {
        float4 wv = *(const float4*)(wp + h * FF + f);
        float4 as = *(const float4*)(ap + h * 2 * FF + f);
        float4 ad = *(const float4*)(ap + h * 2 * FF + FF + f);
        float4 hw = make_float4(xv.x * wv.x, xv.y * wv.y, xv.z * wv.z, xv.w * wv.w);
        float hs = hw.x * as.x + hw.y * as.y + hw.z * as.z + hw.w * as.w;
        float hd = hw.x * ad.x + hw.y * ad.y + hw.z * ad.z + hw.w * ad.w;
        #pragma unroll
        for (int o = 16; o; o >>= 1) {
            hs += __shfl_xor_sync(0xffffffffu, hs, o);
            hd += __shfl_xor_sync(0xffffffffu, hd, o);
        }
        ss[h] = hs; sd[h] = hd;
    }
    if (lane == 0) {
        g_ssrc[gw] = make_float4(ss[0], ss[1], ss[2], ss[3]);
        g_sdst[gw] = make_float4(sd[0], sd[1], sd[2], sd[3]);
    }
}

// ---------------- 5) scatter edges into CSR with precomputed weights ---------
__device__ __forceinline__ float edge_w(float s) {
    return __expf(fminf(-s, -0.2f * s));   // exp(-leaky_relu(s, 0.2))
}
__global__ void k_scatter(const int* __restrict__ ei) {
    int i = blockIdx.x * blockDim.x + threadIdx.x;
    if (i >= NE) return;
    int is64 = g_is64;
    int s = EDGE_SRC(ei, i, is64);
    int d = EDGE_DST(ei, i, is64);
    float4 a4 = g_ssrc[s];
    float4 b4 = g_sdst[d];
    float4 w4 = make_float4(edge_w(a4.x + b4.x), edge_w(a4.y + b4.y),
                            edge_w(a4.z + b4.z), edge_w(a4.w + b4.w));
    int pos = atomicAdd(&g_cursor[s], 1);
    g_sorted_dst[pos] = d;
    g_sorted_w[pos]   = w4;
}

// ---------------- 6) per-node aggregation: one warp/node, 2-edge pipeline ----
__global__ void __launch_bounds__(256) k_agg(const float* __restrict__ x,
                                             const float* __restrict__ wp,
                                             float* __restrict__ out) {
    int gw   = (blockIdx.x * blockDim.x + threadIdx.x) >> 5;
    int lane = threadIdx.x & 31;
    if (gw >= NN) return;
    int beg = g_off[gw], end = g_off[gw + 1];
    int f = lane * 4;

    float4 z = make_float4(0.f, 0.f, 0.f, 0.f);
    float4 a0 = z, a1 = z, a2 = z, a3 = z, rs = z;

    int d0 = 0, d1 = 0;
    float4 e0 = z, e1 = z;
    if (beg < end)     { d0 = __ldcs(&g_sorted_dst[beg]);     e0 = __ldcs(&g_sorted_w[beg]); }
    if (beg + 1 < end) { d1 = __ldcs(&g_sorted_dst[beg + 1]); e1 = __ldcs(&g_sorted_w[beg + 1]); }

    int j = beg;
    while (j + 1 < end) {
        float4 xv0 = __ldg((const float4*)(x + (size_t)d0 * FF + f));
        float4 xv1 = __ldg((const float4*)(x + (size_t)d1 * FF + f));
        int nd0 = d0, nd1 = d1;
        float4 ne0 = e0, ne1 = e1;
        if (j + 3 < end) {
            nd0 = __ldcs(&g_sorted_dst[j + 2]); ne0 = __ldcs(&g_sorted_w[j + 2]);
            nd1 = __ldcs(&g_sorted_dst[j + 3]); ne1 = __ldcs(&g_sorted_w[j + 3]);
        } else if (j + 2 < end) {
            nd0 = __ldcs(&g_sorted_dst[j + 2]); ne0 = __ldcs(&g_sorted_w[j + 2]);
        }
        rs.x += e0.x; rs.y += e0.y; rs.z += e0.z; rs.w += e0.w;
        a0.x += e0.x * xv0.x; a0.y += e0.x * xv0.y; a0.z += e0.x * xv0.z; a0.w += e0.x * xv0.w;
        a1.x += e0.y * xv0.x; a1.y += e0.y * xv0.y; a1.z += e0.y * xv0.z; a1.w += e0.y * xv0.w;
        a2.x += e0.z * xv0.x; a2.y += e0.z * xv0.y; a2.z += e0.z * xv0.z; a2.w += e0.z * xv0.w;
        a3.x += e0.w * xv0.x; a3.y += e0.w * xv0.y; a3.z += e0.w * xv0.z; a3.w += e0.w * xv0.w;
        rs.x += e1.x; rs.y += e1.y; rs.z += e1.z; rs.w += e1.w;
        a0.x += e1.x * xv1.x; a0.y += e1.x * xv1.y; a0.z += e1.x * xv1.z; a0.w += e1.x * xv1.w;
        a1.x += e1.y * xv1.x; a1.y += e1.y * xv1.y; a1.z += e1.y * xv1.z; a1.w += e1.y * xv1.w;
        a2.x += e1.z * xv1.x; a2.y += e1.z * xv1.y; a2.z += e1.z * xv1.z; a2.w += e1.z * xv1.w;
        a3.x += e1.w * xv1.x; a3.y += e1.w * xv1.y; a3.z += e1.w * xv1.z; a3.w += e1.w * xv1.w;
        d0 = nd0; e0 = ne0; d1 = nd1; e1 = ne1;
        j += 2;
    }
    if (j < end) {
        float4 xv = __ldg((const float4*)(x + (size_t)d0 * FF + f));
        rs.x += e0.x; rs.y += e0.y; rs.z += e0.z; rs.w += e0.w;
        a0.x += e0.x * xv.x; a0.y += e0.x * xv.y; a0.z += e0.x * xv.z; a0.w += e0.x * xv.w;
        a1.x += e0.y * xv.x; a1.y += e0.y * xv.y; a1.z += e0.y * xv.z; a1.w += e0.y * xv.w;
        a2.x += e0.z * xv.x; a2.y += e0.z * xv.y; a2.z += e0.z * xv.z; a2.w += e0.z * xv.w;
        a3.x += e0.w * xv.x; a3.y += e0.w * xv.y; a3.z += e0.w * xv.z; a3.w += e0.w * xv.w;
    }

    float i0 = 1.0f / rs.x, i1 = 1.0f / rs.y, i2 = 1.0f / rs.z, i3 = 1.0f / rs.w;
    float4 w0 = *(const float4*)(wp + 0 * FF + f);
    float4 w1 = *(const float4*)(wp + 1 * FF + f);
    float4 w2 = *(const float4*)(wp + 2 * FF + f);
    float4 w3 = *(const float4*)(wp + 3 * FF + f);

    size_t base = (size_t)gw * FF + f;
    __stcs((float4*)(out + 0 * (size_t)NN * FF + base),
        make_float4(a0.x * w0.x * i0, a0.y * w0.y * i0, a0.z * w0.z * i0, a0.w * w0.w * i0));
    __stcs((float4*)(out + 1 * (size_t)NN * FF + base),
        make_float4(a1.x * w1.x * i1, a1.y * w1.y * i1, a1.z * w1.z * i1, a1.w * w1.w * i1));
    __stcs((float4*)(out + 2 * (size_t)NN * FF + base),
        make_float4(a2.x * w2.x * i2, a2.y * w2.y * i2, a2.z * w2.z * i2, a2.w * w2.w * i2));
    __stcs((float4*)(out + 3 * (size_t)NN * FF + base),
        make_float4(a3.x * w3.x * i3, a3.y * w3.y * i3, a3.z * w3.z * i3, a3.w * w3.w * i3));
}

// ---------------- launch -----------------------------------------------------
extern "C" void kernel_launch(void* const* d_in, const int* in_sizes, int n_in,
                              void* d_out, int out_size) {
    const float* x  = (const float*)d_in[0];
    const float* wp = (const float*)d_in[1];
    const float* ap = (const float*)d_in[2];
    const int*   ei = (const int*)d_in[3];
    float* out = (float*)d_out;

    const int TB = 256;
    int edge_blocks = (NE + TB - 1) / TB;       // 6250
    int node_blocks = (NN * 32 + TB - 1) / TB;  // 6250
    int init_blocks = (NN + TB - 1) / TB;       // 196

    k_init<<<init_blocks, TB>>>(ei);
    k_hist<<<edge_blocks, TB>>>(ei);
    k_bsum<<<NBLK, 1024>>>();
    k_bscan<<<1, 64>>>();
    k_scan3<<<NBLK, 1024>>>();
    k_scores<<<node_blocks, TB>>>(x, wp, ap);
    k_scatter<<<edge_blocks, TB>>>(ei);
    k_agg<<<node_blocks, TB>>>(x, wp, out);
}

// round 3
// speedup vs baseline: 1.3194x; 1.0185x over previous
#include <cuda_runtime.h>
#include <cuda_fp16.h>
#include <math.h>

#define NN 50000
#define NE 1600000
#define HH 4
#define FF 128
#define NBLK 49   // ceil(50000/1024)

// ---------------- scratch ----------------------------------------------------
__device__ int    g_is64;
__device__ int    g_deg[NN];
__device__ int    g_off[NN + 1];
__device__ int    g_cursor[NN];
__device__ int    g_bsum[64];
__device__ float4 g_ssrc[NN];
__device__ float4 g_sdst[NN];
__device__ int    g_sorted_dst[NE];
__device__ float4 g_sorted_w[NE];
__device__ __half g_xh[(size_t)NN * FF];   // fp16 copy of x for the gather

// unified edge-index fetch (int64 vs int32 device layout)
__device__ __forceinline__ int EDGE_SRC(const int* p, int i, int is64) {
    return is64 ? p[2 * i] : p[i];
}
__device__ __forceinline__ int EDGE_DST(const int* p, int i, int is64) {
    return is64 ? p[2 * (NE + i)] : p[NE + i];
}

// ---------------- 1) init: zero degrees + dtype detect (block 0) -------------
__global__ void k_init(const int* __restrict__ ei_words) {
    int i = blockIdx.x * blockDim.x + threadIdx.x;
    if (i < NN) g_deg[i] = 0;
    if (i == 0) g_off[NN] = NE;
    if (blockIdx.x == 0) {
        __shared__ int bad;
        if (threadIdx.x == 0) bad = 0;
        __syncthreads();
        for (int k = threadIdx.x; k < 4096; k += blockDim.x)
            if (ei_words[2 * k + 1] != 0) bad = 1;
        __syncthreads();
        if (threadIdx.x == 0) g_is64 = (bad == 0) ? 1 : 0;
    }
}

// ---------------- 2) degree histogram ----------------------------------------
__global__ void k_hist(const int* __restrict__ ei) {
    int i = blockIdx.x * blockDim.x + threadIdx.x;
    if (i >= NE) return;
    atomicAdd(&g_deg[EDGE_SRC(ei, i, g_is64)], 1);
}

// ---------------- 3a) per-block degree sums ----------------------------------
__global__ void k_bsum() {
    __shared__ int wsum[32];
    int b = blockIdx.x, t = threadIdx.x, lane = t & 31, wid = t >> 5;
    int i = b * 1024 + t;
    int v = (i < NN) ? g_deg[i] : 0;
    #pragma unroll
    for (int o = 16; o; o >>= 1) v += __shfl_xor_sync(0xffffffffu, v, o);
    if (lane == 0) wsum[wid] = v;
    __syncthreads();
    if (wid == 0) {
        int s = wsum[lane];
        #pragma unroll
        for (int o = 16; o; o >>= 1) s += __shfl_xor_sync(0xffffffffu, s, o);
        if (lane == 0) g_bsum[b] = s;
    }
}

// ---------------- 3b) per-block scan (computes own 49-prefix inline) ---------
__global__ void k_scan3() {
    __shared__ int wsum[32];
    __shared__ int s2[2];
    int b = blockIdx.x, t = threadIdx.x, lane = t & 31, wid = t >> 5;

    // block offset = sum of g_bsum[0..b-1], computed by first 2 warps
    if (t < 64) {
        int v = (t < b) ? g_bsum[t] : 0;
        #pragma unroll
        for (int o = 16; o; o >>= 1) v += __shfl_xor_sync(0xffffffffu, v, o);
        if (lane == 0) s2[wid] = v;
    }
    __syncthreads();
    int bofs = s2[0] + s2[1];

    int i = b * 1024 + t;
    int v = (i < NN) ? g_deg[i] : 0;
    int inc = v;
    #pragma unroll
    for (int o = 1; o < 32; o <<= 1) {
        int u = __shfl_up_sync(0xffffffffu, inc, o);
        if (lane >= o) inc += u;
    }
    if (lane == 31) wsum[wid] = inc;
    __syncthreads();
    if (wid == 0) {
        int s = wsum[lane];
        #pragma unroll
        for (int o = 1; o < 32; o <<= 1) {
            int u = __shfl_up_sync(0xffffffffu, s, o);
            if (lane >= o) s += u;
        }
        wsum[lane] = s;
    }
    __syncthreads();
    int excl = bofs + (wid ? wsum[wid - 1] : 0) + inc - v;
    if (i < NN) { g_off[i] = excl; g_cursor[i] = excl; }
}

// ---------------- 4) per-node attention scores + fp16 x copy -----------------
__global__ void k_scores(const float* __restrict__ x,
                         const float* __restrict__ wp,
                         const float* __restrict__ ap) {
    int gw   = (blockIdx.x * blockDim.x + threadIdx.x) >> 5;
    int lane = threadIdx.x & 31;
    if (gw >= NN) return;
    int f = lane * 4;
    float4 xv = *(const float4*)(x + (size_t)gw * FF + f);

    // emit fp16 copy (8 B per lane)
    __half2 h01 = __floats2half2_rn(xv.x, xv.y);
    __half2 h23 = __floats2half2_rn(xv.z, xv.w);
    *(__half2*)(g_xh + (size_t)gw * FF + f)     = h01;
    *(__half2*)(g_xh + (size_t)gw * FF + f + 2) = h23;

    float ss[HH], sd[HH];
    #pragma unroll
    for (int h = 0; h < HH; h++) {
        float4 wv = *(const float4*)(wp + h * FF + f);
        float4 as = *(const float4*)(ap + h * 2 * FF + f);
        float4 ad = *(const float4*)(ap + h * 2 * FF + FF + f);
        float4 hw = make_float4(xv.x * wv.x, xv.y * wv.y, xv.z * wv.z, xv.w * wv.w);
        float hs = hw.x * as.x + hw.y * as.y + hw.z * as.z + hw.w * as.w;
        float hd = hw.x * ad.x + hw.y * ad.y + hw.z * ad.z + hw.w * ad.w;
        #pragma unroll
        for (int o = 16; o; o >>= 1) {
            hs += __shfl_xor_sync(0xffffffffu, hs, o);
            hd += __shfl_xor_sync(0xffffffffu, hd, o);
        }
        ss[h] = hs; sd[h] = hd;
    }
    if (lane == 0) {
        g_ssrc[gw] = make_float4(ss[0], ss[1], ss[2], ss[3]);
        g_sdst[gw] = make_float4(sd[0], sd[1], sd[2], sd[3]);
    }
}

// ---------------- 5) scatter edges into CSR with precomputed weights ---------
__device__ __forceinline__ float edge_w(float s) {
    return __expf(fminf(-s, -0.2f * s));   // exp(-leaky_relu(s, 0.2))
}
__global__ void k_scatter(const int* __restrict__ ei) {
    int i = blockIdx.x * blockDim.x + threadIdx.x;
    if (i >= NE) return;
    int is64 = g_is64;
    int s = EDGE_SRC(ei, i, is64);
    int d = EDGE_DST(ei, i, is64);
    float4 a4 = g_ssrc[s];
    float4 b4 = g_sdst[d];
    float4 w4 = make_float4(edge_w(a4.x + b4.x), edge_w(a4.y + b4.y),
                            edge_w(a4.z + b4.z), edge_w(a4.w + b4.w));
    int pos = atomicAdd(&g_cursor[s], 1);
    g_sorted_dst[pos] = d;
    g_sorted_w[pos]   = w4;
}

// ---------------- 6) aggregation: one warp/node, fp16 gather, 2-edge pipe ----
__device__ __forceinline__ float4 load_xh(int d, int f) {
    float2 raw = *(const float2*)(g_xh + (size_t)d * FF + f);
    __half2 h01 = *reinterpret_cast<__half2*>(&raw.x);
    __half2 h23 = *reinterpret_cast<__half2*>(&raw.y);
    float2 f01 = __half22float2(h01);
    float2 f23 = __half22float2(h23);
    return make_float4(f01.x, f01.y, f23.x, f23.y);
}

__global__ void __launch_bounds__(256) k_agg(const float* __restrict__ wp,
                                             float* __restrict__ out) {
    int gw   = (blockIdx.x * blockDim.x + threadIdx.x) >> 5;
    int lane = threadIdx.x & 31;
    if (gw >= NN) return;
    int beg = g_off[gw], end = g_off[gw + 1];
    int f = lane * 4;

    float4 z = make_float4(0.f, 0.f, 0.f, 0.f);
    float4 a0 = z, a1 = z, a2 = z, a3 = z, rs = z;

    int d0 = 0, d1 = 0;
    float4 e0 = z, e1 = z;
    if (beg < end)     { d0 = __ldcs(&g_sorted_dst[beg]);     e0 = __ldcs(&g_sorted_w[beg]); }
    if (beg + 1 < end) { d1 = __ldcs(&g_sorted_dst[beg + 1]); e1 = __ldcs(&g_sorted_w[beg + 1]); }

    int j = beg;
    while (j + 1 < end) {
        float4 xv0 = load_xh(d0, f);
        float4 xv1 = load_xh(d1, f);
        int nd0 = d0, nd1 = d1;
        float4 ne0 = e0, ne1 = e1;
        if (j + 3 < end) {
            nd0 = __ldcs(&g_sorted_dst[j + 2]); ne0 = __ldcs(&g_sorted_w[j + 2]);
            nd1 = __ldcs(&g_sorted_dst[j + 3]); ne1 = __ldcs(&g_sorted_w[j + 3]);
        } else if (j + 2 < end) {
            nd0 = __ldcs(&g_sorted_dst[j + 2]); ne0 = __ldcs(&g_sorted_w[j + 2]);
        }
        rs.x += e0.x; rs.y += e0.y; rs.z += e0.z; rs.w += e0.w;
        a0.x += e0.x * xv0.x; a0.y += e0.x * xv0.y; a0.z += e0.x * xv0.z; a0.w += e0.x * xv0.w;
        a1.x += e0.y * xv0.x; a1.y += e0.y * xv0.y; a1.z += e0.y * xv0.z; a1.w += e0.y * xv0.w;
        a2.x += e0.z * xv0.x; a2.y += e0.z * xv0.y; a2.z += e0.z * xv0.z; a2.w += e0.z * xv0.w;
        a3.x += e0.w * xv0.x; a3.y += e0.w * xv0.y; a3.z += e0.w * xv0.z; a3.w += e0.w * xv0.w;
        rs.x += e1.x; rs.y += e1.y; rs.z += e1.z; rs.w += e1.w;
        a0.x += e1.x * xv1.x; a0.y += e1.x * xv1.y; a0.z += e1.x * xv1.z; a0.w += e1.x * xv1.w;
        a1.x += e1.y * xv1.x; a1.y += e1.y * xv1.y; a1.z += e1.y * xv1.z; a1.w += e1.y * xv1.w;
        a2.x += e1.z * xv1.x; a2.y += e1.z * xv1.y; a2.z += e1.z * xv1.z; a2.w += e1.z * xv1.w;
        a3.x += e1.w * xv1.x; a3.y += e1.w * xv1.y; a3.z += e1.w * xv1.z; a3.w += e1.w * xv1.w;
        d0 = nd0; e0 = ne0; d1 = nd1; e1 = ne1;
        j += 2;
    }
    if (j < end) {
        float4 xv = load_xh(d0, f);
        rs.x += e0.x; rs.y += e0.y; rs.z += e0.z; rs.w += e0.w;
        a0.x += e0.x * xv.x; a0.y += e0.x * xv.y; a0.z += e0.x * xv.z; a0.w += e0.x * xv.w;
        a1.x += e0.y * xv.x; a1.y += e0.y * xv.y; a1.z += e0.y * xv.z; a1.w += e0.y * xv.w;
        a2.x += e0.z * xv.x; a2.y += e0.z * xv.y; a2.z += e0.z * xv.z; a2.w += e0.z * xv.w;
        a3.x += e0.w * xv.x; a3.y += e0.w * xv.y; a3.z += e0.w * xv.z; a3.w += e0.w * xv.w;
    }

    float i0 = 1.0f / rs.x, i1 = 1.0f / rs.y, i2 = 1.0f / rs.z, i3 = 1.0f / rs.w;
    float4 w0 = *(const float4*)(wp + 0 * FF + f);
    float4 w1 = *(const float4*)(wp + 1 * FF + f);
    float4 w2 = *(const float4*)(wp + 2 * FF + f);
    float4 w3 = *(const float4*)(wp + 3 * FF + f);

    size_t base = (size_t)gw * FF + f;
    __stcs((float4*)(out + 0 * (size_t)NN * FF + base),
        make_float4(a0.x * w0.x * i0, a0.y * w0.y * i0, a0.z * w0.z * i0, a0.w * w0.w * i0));
    __stcs((float4*)(out + 1 * (size_t)NN * FF + base),
        make_float4(a1.x * w1.x * i1, a1.y * w1.y * i1, a1.z * w1.z * i1, a1.w * w1.w * i1));
    __stcs((float4*)(out + 2 * (size_t)NN * FF + base),
        make_float4(a2.x * w2.x * i2, a2.y * w2.y * i2, a2.z * w2.z * i2, a2.w * w2.w * i2));
    __stcs((float4*)(out + 3 * (size_t)NN * FF + base),
        make_float4(a3.x * w3.x * i3, a3.y * w3.y * i3, a3.z * w3.z * i3, a3.w * w3.w * i3));
}

// ---------------- launch -----------------------------------------------------
extern "C" void kernel_launch(void* const* d_in, const int* in_sizes, int n_in,
                              void* d_out, int out_size) {
    const float* x  = (const float*)d_in[0];
    const float* wp = (const float*)d_in[1];
    const float* ap = (const float*)d_in[2];
    const int*   ei = (const int*)d_in[3];
    float* out = (float*)d_out;

    const int TB = 256;
    int edge_blocks = (NE + TB - 1) / TB;       // 6250
    int node_blocks = (NN * 32 + TB - 1) / TB;  // 6250
    int init_blocks = (NN + TB - 1) / TB;       // 196

    k_init<<<init_blocks, TB>>>(ei);
    k_hist<<<edge_blocks, TB>>>(ei);
    k_bsum<<<NBLK, 1024>>>();
    k_scan3<<<NBLK, 1024>>>();
    k_scores<<<node_blocks, TB>>>(x, wp, ap);
    k_scatter<<<edge_blocks, TB>>>(ei);
    k_agg<<<node_blocks, TB>>>(wp, out);
}

// round 5
// speedup vs baseline: 1.4496x; 1.0986x over previous
#include <cuda_runtime.h>
#include <cuda_fp16.h>
#include <math.h>

#define NN 50000
#define NE 1600000
#define HH 4
#define FF 128
#define NBLK 49   // ceil(50000/1024)

typedef unsigned long long u64;

// ---------------- scratch ----------------------------------------------------
__device__ int    g_is64;
__device__ int    g_deg[NN];
__device__ int    g_off[NN + 1];
__device__ int    g_cursor[NN];
__device__ float4 g_ssrc[NN];
__device__ float4 g_sdst[NN];
__device__ int4   g_edges[NE];            // {half2 w01, half2 w23, dst, pad}
__device__ __half g_xh[(size_t)NN * FF];  // fp16 copy of x

// ---------------- f32x2 helpers (B300 packed fp32) ---------------------------
__device__ __forceinline__ u64 pack2(float a, float b) {
    u64 r; asm("mov.b64 %0,{%1,%2};" : "=l"(r) : "f"(a), "f"(b)); return r;
}
__device__ __forceinline__ u64 dup2(float a) { return pack2(a, a); }
__device__ __forceinline__ void unpk2(u64 v, float& a, float& b) {
    asm("mov.b64 {%0,%1},%2;" : "=f"(a), "=f"(b) : "l"(v));
}
__device__ __forceinline__ u64 ffma2(u64 a, u64 b, u64 c) {
    u64 d; asm("fma.rn.f32x2 %0,%1,%2,%3;" : "=l"(d) : "l"(a), "l"(b), "l"(c)); return d;
}
__device__ __forceinline__ u64 fadd2(u64 a, u64 b) {
    u64 d; asm("add.rn.f32x2 %0,%1,%2;" : "=l"(d) : "l"(a), "l"(b)); return d;
}

__device__ __forceinline__ int EDGE_SRC(const int* p, int i, int is64) {
    return is64 ? p[2 * i] : p[i];
}
__device__ __forceinline__ int EDGE_DST(const int* p, int i, int is64) {
    return is64 ? p[2 * (NE + i)] : p[NE + i];
}

// ---------------- 1) prep: zero deg + detect + scores + fp16 x copy ----------
__global__ void k_prep(const float* __restrict__ x,
                       const float* __restrict__ wp,
                       const float* __restrict__ ap,
                       const int* __restrict__ ei_words) {
    int tid = blockIdx.x * blockDim.x + threadIdx.x;
    if (tid < NN) g_deg[tid] = 0;
    if (tid == 0) g_off[NN] = NE;
    if (blockIdx.x == 0) {
        __shared__ int bad;
        if (threadIdx.x == 0) bad = 0;
        __syncthreads();
        for (int k = threadIdx.x; k < 4096; k += blockDim.x)
            if (ei_words[2 * k + 1] != 0) bad = 1;
        __syncthreads();
        if (threadIdx.x == 0) g_is64 = (bad == 0) ? 1 : 0;
    }

    int gw   = tid >> 5;
    int lane = threadIdx.x & 31;
    if (gw >= NN) return;
    int f = lane * 4;
    float4 xv = *(const float4*)(x + (size_t)gw * FF + f);

    // fp16 copy
    *(__half2*)(g_xh + (size_t)gw * FF + f)     = __floats2half2_rn(xv.x, xv.y);
    *(__half2*)(g_xh + (size_t)gw * FF + f + 2) = __floats2half2_rn(xv.z, xv.w);

    float ss[HH], sd[HH];
    #pragma unroll
    for (int h = 0; h < HH; h++) {
        float4 wv = *(const float4*)(wp + h * FF + f);
        float4 as = *(const float4*)(ap + h * 2 * FF + f);
        float4 ad = *(const float4*)(ap + h * 2 * FF + FF + f);
        float4 hw = make_float4(xv.x * wv.x, xv.y * wv.y, xv.z * wv.z, xv.w * wv.w);
        float hs = hw.x * as.x + hw.y * as.y + hw.z * as.z + hw.w * as.w;
        float hd = hw.x * ad.x + hw.y * ad.y + hw.z * ad.z + hw.w * ad.w;
        #pragma unroll
        for (int o = 16; o; o >>= 1) {
            hs += __shfl_xor_sync(0xffffffffu, hs, o);
            hd += __shfl_xor_sync(0xffffffffu, hd, o);
        }
        ss[h] = hs; sd[h] = hd;
    }
    if (lane == 0) {
        g_ssrc[gw] = make_float4(ss[0], ss[1], ss[2], ss[3]);
        g_sdst[gw] = make_float4(sd[0], sd[1], sd[2], sd[3]);
    }
}

// ---------------- 2) degree histogram ----------------------------------------
__global__ void k_hist(const int* __restrict__ ei) {
    int i = blockIdx.x * blockDim.x + threadIdx.x;
    if (i >= NE) return;
    atomicAdd(&g_deg[EDGE_SRC(ei, i, g_is64)], 1);
}

// ---------------- 3) one-shot scan: each block sums its own prefix -----------
__global__ void k_scan() {
    __shared__ int wsum[32];
    __shared__ int redsum[32];
    int b = blockIdx.x, t = threadIdx.x, lane = t & 31, wid = t >> 5;

    // block offset = sum of deg[0 .. b*1024), strided coalesced read
    int pre = b * 1024;
    int acc = 0;
    for (int i = t; i < pre; i += 1024) acc += g_deg[i];
    #pragma unroll
    for (int o = 16; o; o >>= 1) acc += __shfl_xor_sync(0xffffffffu, acc, o);
    if (lane == 0) redsum[wid] = acc;
    __syncthreads();
    int bofs;
    {
        int v = (lane < 32) ? redsum[lane] : 0;
        #pragma unroll
        for (int o = 16; o; o >>= 1) v += __shfl_xor_sync(0xffffffffu, v, o);
        bofs = __shfl_sync(0xffffffffu, v, 0);
    }

    int i = pre + t;
    int v = (i < NN) ? g_deg[i] : 0;
    int inc = v;
    #pragma unroll
    for (int o = 1; o < 32; o <<= 1) {
        int u = __shfl_up_sync(0xffffffffu, inc, o);
        if (lane >= o) inc += u;
    }
    if (lane == 31) wsum[wid] = inc;
    __syncthreads();
    if (wid == 0) {
        int s = wsum[lane];
        #pragma unroll
        for (int o = 1; o < 32; o <<= 1) {
            int u = __shfl_up_sync(0xffffffffu, s, o);
            if (lane >= o) s += u;
        }
        wsum[lane] = s;
    }
    __syncthreads();
    int excl = bofs + (wid ? wsum[wid - 1] : 0) + inc - v;
    if (i < NN) { g_off[i] = excl; g_cursor[i] = excl; }
}

// ---------------- 4) scatter: packed 16B records ------------------------------
__device__ __forceinline__ float edge_w(float s) {
    return __expf(fminf(-s, -0.2f * s));   // exp(-leaky_relu(s, 0.2))
}
__global__ void k_scatter(const int* __restrict__ ei) {
    int i = blockIdx.x * blockDim.x + threadIdx.x;
    if (i >= NE) return;
    int is64 = g_is64;
    int s = EDGE_SRC(ei, i, is64);
    int d = EDGE_DST(ei, i, is64);
    float4 a4 = g_ssrc[s];
    float4 b4 = g_sdst[d];
    __half2 w01 = __floats2half2_rn(edge_w(a4.x + b4.x), edge_w(a4.y + b4.y));
    __half2 w23 = __floats2half2_rn(edge_w(a4.z + b4.z), edge_w(a4.w + b4.w));
    int4 rec;
    rec.x = *reinterpret_cast<int*>(&w01);
    rec.y = *reinterpret_cast<int*>(&w23);
    rec.z = d;
    rec.w = 0;
    int pos = atomicAdd(&g_cursor[s], 1);
    g_edges[pos] = rec;
}

// ---------------- 5) aggregation: warp/node, f32x2 FMA, 4-wide pipeline ------
__global__ void __launch_bounds__(256) k_agg(const float* __restrict__ wp,
                                             float* __restrict__ out) {
    int gw   = (blockIdx.x * blockDim.x + threadIdx.x) >> 5;
    int lane = threadIdx.x & 31;
    if (gw >= NN) return;
    int beg = g_off[gw];
    int n   = g_off[gw + 1] - beg;
    int f = lane * 4;
    const int4* ep = g_edges + beg;

    u64 acc[HH][2];
    #pragma unroll
    for (int h = 0; h < HH; h++) { acc[h][0] = 0ull; acc[h][1] = 0ull; }
    u64 rs01 = 0ull, rs23 = 0ull;

    int4 r[4];
    #pragma unroll
    for (int k = 0; k < 4; k++)
        r[k] = (k < n) ? __ldcs(ep + k) : make_int4(0, 0, 0, 0);

    for (int c = 0; c < n; c += 4) {
        // 4 independent x gathers (8B each)
        int2 xr[4];
        #pragma unroll
        for (int k = 0; k < 4; k++)
            xr[k] = __ldg((const int2*)(g_xh + (size_t)r[k].z * FF + f));
        // prefetch next chunk of records
        int4 nx[4];
        #pragma unroll
        for (int k = 0; k < 4; k++) {
            int idx = c + 4 + k;
            nx[k] = (idx < n) ? __ldcs(ep + idx) : make_int4(0, 0, 0, 0);
        }
        // math
        #pragma unroll
        for (int k = 0; k < 4; k++) {
            __half2 hw01 = *reinterpret_cast<__half2*>(&r[k].x);
            __half2 hw23 = *reinterpret_cast<__half2*>(&r[k].y);
            float2 w01 = __half22float2(hw01);
            float2 w23 = __half22float2(hw23);
            rs01 = fadd2(rs01, pack2(w01.x, w01.y));
            rs23 = fadd2(rs23, pack2(w23.x, w23.y));
            __half2 hx01 = *reinterpret_cast<__half2*>(&xr[k].x);
            __half2 hx23 = *reinterpret_cast<__half2*>(&xr[k].y);
            float2 x01 = __half22float2(hx01);
            float2 x23 = __half22float2(hx23);
            u64 xv01 = pack2(x01.x, x01.y);
            u64 xv23 = pack2(x23.x, x23.y);
            u64 p0 = dup2(w01.x), p1 = dup2(w01.y), p2 = dup2(w23.x), p3 = dup2(w23.y);
            acc[0][0] = ffma2(p0, xv01, acc[0][0]); acc[0][1] = ffma2(p0, xv23, acc[0][1]);
            acc[1][0] = ffma2(p1, xv01, acc[1][0]); acc[1][1] = ffma2(p1, xv23, acc[1][1]);
            acc[2][0] = ffma2(p2, xv01, acc[2][0]); acc[2][1] = ffma2(p2, xv23, acc[2][1]);
            acc[3][0] = ffma2(p3, xv01, acc[3][0]); acc[3][1] = ffma2(p3, xv23, acc[3][1]);
        }
        #pragma unroll
        for (int k = 0; k < 4; k++) r[k] = nx[k];
    }

    float rs0, rs1, rs2, rs3;
    unpk2(rs01, rs0, rs1); unpk2(rs23, rs2, rs3);
    float inv[HH] = {1.0f / rs0, 1.0f / rs1, 1.0f / rs2, 1.0f / rs3};

    size_t base = (size_t)gw * FF + f;
    #pragma unroll
    for (int h = 0; h < HH; h++) {
        float4 wv = *(const float4*)(wp + h * FF + f);
        float a0, a1, a2, a3;
        unpk2(acc[h][0], a0, a1); unpk2(acc[h][1], a2, a3);
        __stcs((float4*)(out + (size_t)h * NN * FF + base),
            make_float4(a0 * wv.x * inv[h], a1 * wv.y * inv[h],
                        a2 * wv.z * inv[h], a3 * wv.w * inv[h]));
    }
}

// ---------------- launch -----------------------------------------------------
extern "C" void kernel_launch(void* const* d_in, const int* in_sizes, int n_in,
                              void* d_out, int out_size) {
    const float* x  = (const float*)d_in[0];
    const float* wp = (const float*)d_in[1];
    const float* ap = (const float*)d_in[2];
    const int*   ei = (const int*)d_in[3];
    float* out = (float*)d_out;

    const int TB = 256;
    int edge_blocks = (NE + TB - 1) / TB;       // 6250
    int node_blocks = (NN * 32 + TB - 1) / TB;  // 6250

    k_prep<<<node_blocks, TB>>>(x, wp, ap, ei);
    k_hist<<<edge_blocks, TB>>>(ei);
    k_scan<<<NBLK, 1024>>>();
    k_scatter<<<edge_blocks, TB>>>(ei);
    k_agg<<<node_blocks, TB>>>(wp, out);
}